// round 2
// baseline (speedup 1.0000x reference)
#include <cuda_runtime.h>
#include <cstdint>
#include <cstddef>

#define FULLMASK 0xffffffffu

// ---------------- problem constants (fixed by the benchmark) ----------------
constexpr int Bc  = 2;
constexpr int Hc  = 8;
constexpr int Sc  = 2048;
constexpr int Dc  = 128;
constexpr int Mc  = 32768;
constexpr int NQ  = Bc * Sc;      // 4096 queries per head
// ---------------- tiling ----------------
constexpr int TQ  = 64;           // queries per block
constexpr int TK  = 128;          // keys per tile
constexpr int DCH = 32;           // d-chunk staged in shared
constexpr int NTILES = Mc / TK;   // 256
constexpr int NCH = Dc / DCH;     // 4 chunks per tile

// ---------------- packed fp32x2 helpers (Blackwell full-rate fp32) ----------
static __device__ __forceinline__ void fma2(unsigned long long& acc,
                                            unsigned long long a,
                                            unsigned long long b) {
    asm("fma.rn.f32x2 %0, %1, %2, %0;" : "+l"(acc) : "l"(a), "l"(b));
}
static __device__ __forceinline__ unsigned long long pack2(float a) {
    unsigned long long r;
    asm("mov.b64 %0, {%1, %1};" : "=l"(r) : "f"(a));
    return r;
}
static __device__ __forceinline__ float2 unpack2(unsigned long long v) {
    float2 r;
    asm("mov.b64 {%0, %1}, %2;" : "=f"(r.x), "=f"(r.y) : "l"(v));
    return r;
}

__global__ __launch_bounds__(256, 2)
void praxis_fused_kernel(const float* __restrict__ Q,      // [B,H,S,D]
                         const float* __restrict__ Outp,   // [B,H,S,D]
                         const float* __restrict__ Gate,   // [H]
                         const float* __restrict__ Kmem,   // [H,M,D] (pre-normalized)
                         const float* __restrict__ Vmem,   // [H,M,D]
                         float* __restrict__ Out)          // [B,H,S,D]
{
    extern __shared__ float smem[];
    float* Qs = smem;                  // [Dc][TQ]  transposed, normalized queries
    float* Ks = smem + Dc * TQ;        // [2][DCH][TK] transposed key d-chunks

    const int tid   = threadIdx.x;
    const int tx    = tid & 15;        // key group   (16)
    const int ty    = tid >> 4;        // query group (16)
    const int lane  = tid & 31;
    const int h     = blockIdx.y;
    const int qtile = blockIdx.x;
    const int q0    = qtile * TQ;

    const float* KH = Kmem + (size_t)h * Mc * Dc;

    // ---------------- load + l2-normalize the Q tile into Qs[d][q] ----------
    {
        const int q    = tid >> 2;          // 0..63
        const int part = tid & 3;           // quarter of the 128-dim vector
        const int qg   = q0 + q;
        const int bq   = qg >> 11;          // qg / 2048
        const int sq   = qg & 2047;
        const float* qp = Q + ((((size_t)bq * Hc + h) * Sc + sq) * Dc) + part * 32;
        float4 v[8];
        float ss = 0.f;
        #pragma unroll
        for (int r = 0; r < 8; ++r) {
            v[r] = reinterpret_cast<const float4*>(qp)[r];
            ss += v[r].x * v[r].x + v[r].y * v[r].y + v[r].z * v[r].z + v[r].w * v[r].w;
        }
        ss += __shfl_xor_sync(FULLMASK, ss, 1);
        ss += __shfl_xor_sync(FULLMASK, ss, 2);
        const float inv = 1.0f / fmaxf(sqrtf(ss), 1e-12f);
        #pragma unroll
        for (int r = 0; r < 8; ++r) {
            const int d = part * 32 + r * 4;
            Qs[(d + 0) * TQ + q] = v[r].x * inv;
            Qs[(d + 1) * TQ + q] = v[r].y * inv;
            Qs[(d + 2) * TQ + q] = v[r].z * inv;
            Qs[(d + 3) * TQ + q] = v[r].w * inv;
        }
    }

    // copy-lane assignment for K staging (transpose on the fly)
    const int ck = tid & 127;          // key row within tile
    const int cg = tid >> 7;           // 0..1 : which float4 pair of the 32-d chunk

    // ---------------- prologue: stage (tile 0, chunk 0) into buffer 0 -------
    {
        const float* src = KH + (size_t)ck * Dc + cg * 4;
        #pragma unroll
        for (int m = 0; m < 4; ++m) {
            const float4 p = *reinterpret_cast<const float4*>(src + 8 * m);
            const int dd = cg * 4 + 8 * m;
            Ks[(dd + 0) * TK + ck] = p.x;
            Ks[(dd + 1) * TK + ck] = p.y;
            Ks[(dd + 2) * TK + ck] = p.z;
            Ks[(dd + 3) * TK + ck] = p.w;
        }
    }
    __syncthreads();

    // ---------------- running top-16, distributed one entry per half-warp lane
    float store_s[4];
    int   store_i[4];
    float thr[4];
    #pragma unroll
    for (int i = 0; i < 4; ++i) { store_s[i] = -1e30f; store_i[i] = 0; thr[i] = -1e30f; }
    const unsigned hm = (lane < 16) ? 0x0000FFFFu : 0xFFFF0000u;

    unsigned long long acc[4][4];
    #pragma unroll
    for (int i = 0; i < 4; ++i)
        #pragma unroll
        for (int j = 0; j < 4; ++j) acc[i][j] = 0ULL;

    int buf = 0;

    // ---------------- main loop over key tiles -----------------------------
    for (int kt = 0; kt < NTILES; ++kt) {
        #pragma unroll 1
        for (int c = 0; c < NCH; ++c) {
            // -- prefetch next chunk (possibly chunk 0 of next tile) into regs
            const int nc  = (c + 1) & 3;
            const int nkt = kt + ((c + 1) >> 2);
            const bool hn = (nkt < NTILES);
            float4 pf0, pf1, pf2, pf3;
            if (hn) {
                const float* src = KH + ((size_t)(nkt * TK + ck)) * Dc + nc * DCH + cg * 4;
                pf0 = *reinterpret_cast<const float4*>(src + 0);
                pf1 = *reinterpret_cast<const float4*>(src + 8);
                pf2 = *reinterpret_cast<const float4*>(src + 16);
                pf3 = *reinterpret_cast<const float4*>(src + 24);
            }

            // -- compute this chunk: 4q x 8k per thread, packed f32x2 --------
            const float* ksb = Ks + buf * (DCH * TK);
            #pragma unroll
            for (int dd = 0; dd < DCH; ++dd) {
                const int gd = c * DCH + dd;
                const float4 av = *reinterpret_cast<const float4*>(Qs + gd * TQ + 4 * ty);
                const float* kr = ksb + dd * TK;
                const ulonglong2 b01 = *reinterpret_cast<const ulonglong2*>(kr + 4 * tx);
                const ulonglong2 b23 = *reinterpret_cast<const ulonglong2*>(kr + 64 + 4 * tx);
                unsigned long long aa;
                aa = pack2(av.x);
                fma2(acc[0][0], aa, b01.x); fma2(acc[0][1], aa, b01.y);
                fma2(acc[0][2], aa, b23.x); fma2(acc[0][3], aa, b23.y);
                aa = pack2(av.y);
                fma2(acc[1][0], aa, b01.x); fma2(acc[1][1], aa, b01.y);
                fma2(acc[1][2], aa, b23.x); fma2(acc[1][3], aa, b23.y);
                aa = pack2(av.z);
                fma2(acc[2][0], aa, b01.x); fma2(acc[2][1], aa, b01.y);
                fma2(acc[2][2], aa, b23.x); fma2(acc[2][3], aa, b23.y);
                aa = pack2(av.w);
                fma2(acc[3][0], aa, b01.x); fma2(acc[3][1], aa, b01.y);
                fma2(acc[3][2], aa, b23.x); fma2(acc[3][3], aa, b23.y);
            }

            // -- drain prefetch into the other buffer (transposed) -----------
            if (hn) {
                float* kd = Ks + (buf ^ 1) * (DCH * TK);
                const int db = cg * 4;
                kd[(db + 0)  * TK + ck] = pf0.x;  kd[(db + 1)  * TK + ck] = pf0.y;
                kd[(db + 2)  * TK + ck] = pf0.z;  kd[(db + 3)  * TK + ck] = pf0.w;
                kd[(db + 8)  * TK + ck] = pf1.x;  kd[(db + 9)  * TK + ck] = pf1.y;
                kd[(db + 10) * TK + ck] = pf1.z;  kd[(db + 11) * TK + ck] = pf1.w;
                kd[(db + 16) * TK + ck] = pf2.x;  kd[(db + 17) * TK + ck] = pf2.y;
                kd[(db + 18) * TK + ck] = pf2.z;  kd[(db + 19) * TK + ck] = pf2.w;
                kd[(db + 24) * TK + ck] = pf3.x;  kd[(db + 25) * TK + ck] = pf3.y;
                kd[(db + 26) * TK + ck] = pf3.z;  kd[(db + 27) * TK + ck] = pf3.w;
            }
            __syncthreads();
            buf ^= 1;
        }

        // ---------------- top-16 update for this tile -----------------------
        const int kbase = kt * TK;
        #pragma unroll
        for (int i = 0; i < 4; ++i) {
            const float2 u0 = unpack2(acc[i][0]);
            const float2 u1 = unpack2(acc[i][1]);
            const float2 u2 = unpack2(acc[i][2]);
            const float2 u3 = unpack2(acc[i][3]);
            float sims[8] = { u0.x, u0.y, u1.x, u1.y, u2.x, u2.y, u3.x, u3.y };

            // fast path: warp ballot on per-thread row max vs threshold
            float mx = sims[0];
            #pragma unroll
            for (int jj = 1; jj < 8; ++jj) mx = fmaxf(mx, sims[jj]);
            const unsigned bal = __ballot_sync(FULLMASK, mx > thr[i]);
            if (bal) {
                #pragma unroll
                for (int jj = 0; jj < 8; ++jj) {
                    const float s = sims[jj];
                    const int kidx = kbase + ((jj < 4) ? (4 * tx + jj)
                                                       : (64 + 4 * tx + (jj - 4)));
                    bool pending = s > thr[i];
                    unsigned ball;
                    while ((ball = __ballot_sync(FULLMASK, pending)) != 0) {
                        const unsigned bh = ball & hm;
                        const int src = bh ? (__ffs(bh) - 1) : lane;
                        const float cs = __shfl_sync(FULLMASK, s, src);
                        const int   ci = __shfl_sync(FULLMASK, kidx, src);
                        // locate min entry within the 16-lane half
                        float mv = store_s[i];
                        int   ml = lane;
                        #pragma unroll
                        for (int o = 1; o < 16; o <<= 1) {
                            const float ov = __shfl_xor_sync(FULLMASK, mv, o);
                            const int   ol = __shfl_xor_sync(FULLMASK, ml, o);
                            if (ov < mv || (ov == mv && ol < ml)) { mv = ov; ml = ol; }
                        }
                        if (bh && lane == ml) { store_s[i] = cs; store_i[i] = ci; }
                        // recompute threshold = new min of the half's 16 entries
                        float t = store_s[i];
                        #pragma unroll
                        for (int o = 1; o < 16; o <<= 1)
                            t = fminf(t, __shfl_xor_sync(FULLMASK, t, o));
                        if (bh) {
                            thr[i] = t;
                            if (lane == src) pending = false;
                            pending = pending && (s > thr[i]);
                        }
                    }
                }
            }
            acc[i][0] = 0ULL; acc[i][1] = 0ULL; acc[i][2] = 0ULL; acc[i][3] = 0ULL;
        }
    }

    // ---------------- epilogue: gather V, weighted sum, gate blend ----------
    const int hl = lane & 15;                       // lane within half-warp
    const float gv = Gate[h];
    const float g  = 1.0f / (1.0f + expf(-gv));
    const float og = 1.0f - g;
    const float* VH = Vmem + (size_t)h * Mc * Dc;

    #pragma unroll
    for (int i = 0; i < 4; ++i) {
        const int qg = q0 + 4 * ty + i;
        const int bq = qg >> 11;
        const int sq = qg & 2047;
        float a[8] = {0.f, 0.f, 0.f, 0.f, 0.f, 0.f, 0.f, 0.f};
        #pragma unroll
        for (int j = 0; j < 16; ++j) {
            const int src = (lane & 16) | j;
            const float sj = __shfl_sync(FULLMASK, store_s[i], src);
            const int   vj = __shfl_sync(FULLMASK, store_i[i], src);
            const float4* vp = reinterpret_cast<const float4*>(VH + (size_t)vj * Dc + hl * 8);
            const float4 v0 = vp[0];
            const float4 v1 = vp[1];
            a[0] += sj * v0.x; a[1] += sj * v0.y; a[2] += sj * v0.z; a[3] += sj * v0.w;
            a[4] += sj * v1.x; a[5] += sj * v1.y; a[6] += sj * v1.z; a[7] += sj * v1.w;
        }
        const size_t off = (((size_t)bq * Hc + h) * Sc + sq) * Dc + hl * 8;
        const float4 o0 = *reinterpret_cast<const float4*>(Outp + off);
        const float4 o1 = *reinterpret_cast<const float4*>(Outp + off + 4);
        float4 r0, r1;
        r0.x = g * a[0] + og * o0.x;  r0.y = g * a[1] + og * o0.y;
        r0.z = g * a[2] + og * o0.z;  r0.w = g * a[3] + og * o0.w;
        r1.x = g * a[4] + og * o1.x;  r1.y = g * a[5] + og * o1.y;
        r1.z = g * a[6] + og * o1.z;  r1.w = g * a[7] + og * o1.w;
        *reinterpret_cast<float4*>(Out + off)     = r0;
        *reinterpret_cast<float4*>(Out + off + 4) = r1;
    }
}

extern "C" void kernel_launch(void* const* d_in, const int* in_sizes, int n_in,
                              void* d_out, int out_size) {
    // metadata order: inputs(0), query(1), key(2), value(3), outputs(4),
    //                 gate(5), key_memories(6), value_memories(7)
    const float* query   = (const float*)d_in[1];
    const float* outputs = (const float*)d_in[4];
    const float* gate    = (const float*)d_in[5];
    const float* kmem    = (const float*)d_in[6];
    const float* vmem    = (const float*)d_in[7];
    float* out = (float*)d_out;

    const int smem_bytes = (Dc * TQ + 2 * DCH * TK) * (int)sizeof(float);  // 64 KB
    cudaFuncSetAttribute(praxis_fused_kernel,
                         cudaFuncAttributeMaxDynamicSharedMemorySize, smem_bytes);

    dim3 grid(NQ / TQ, Hc);   // 64 query tiles x 8 heads = 512 blocks
    praxis_fused_kernel<<<grid, 256, smem_bytes>>>(query, outputs, gate, kmem, vmem, out);
}